// round 16
// baseline (speedup 1.0000x reference)
#include <cuda_runtime.h>

// Problem constants (shapes fixed by the benchmark instance)
#define W_IN      128
#define UP_FACTOR 8
#define SIZE      (W_IN * UP_FACTOR)   // 1024 interpolated points
#define NTHREADS  256
#define NWARP     (NTHREADS / 32)
#define QPT       (SIZE / NTHREADS)    // 4 queries per thread
#define NSPLIT    4                    // candidate slices per task
#define SLICE     (SIZE / NSPLIT)      // 256 candidates per slice
#define NGRP_L    (SLICE / 16)         // 16 groups per slice
#define GRPQ      4                    // quads per group
#define GRP       16                   // candidates per group
#define MAXTASKS  256
#define POINT_ORDER_WEIGHT 0.1f

typedef unsigned long long u64;

// ---- Blackwell packed f32x2 helpers (sm_103a) ----
__device__ __forceinline__ u64 pk2(float lo, float hi) {
    u64 r; asm("mov.b64 %0, {%1, %2};" : "=l"(r) : "f"(lo), "f"(hi)); return r;
}
__device__ __forceinline__ u64 fma2(u64 a, u64 b, u64 c) {
    u64 r; asm("fma.rn.f32x2 %0, %1, %2, %3;" : "=l"(r) : "l"(a), "l"(b), "l"(c)); return r;
}
__device__ __forceinline__ void unpk2(u64 v, unsigned &lo, unsigned &hi) {
    asm("mov.b64 {%0, %1}, %2;" : "=r"(lo), "=r"(hi) : "l"(v));
}

// Deterministic cross-CTA state (all reset by their last users each call)
__device__ float4   g_part[MAXTASKS];
__device__ unsigned g_done;                       // zero-init
__device__ unsigned g_tdone[MAXTASKS];            // zero-init
__device__ float    g_cand[MAXTASKS * 3 * SIZE];  // per task: [cx|cy|cn+B] x 1024
__device__ unsigned g_key[MAXTASKS * NSPLIT * SIZE];

__global__ __launch_bounds__(NTHREADS, 7)
void chamfer_split_kernel(const float* __restrict__ tgt,
                          const float* __restrict__ pred,
                          const float* __restrict__ vis,
                          float* __restrict__ out,
                          int N)
{
    const int blk   = blockIdx.x;
    const int task  = blk >> 2;           // (n, dir)
    const int split = blk & 3;
    const int n     = task >> 1;
    const int dir   = task & 1;
    const int tid   = threadIdx.x;

    // During scan: sh_c* hold this CTA's 256-candidate slice at [0,256).
    // Combiner reloads the FULL 1024 candidates into the same arrays.
    __shared__ __align__(16) float sh_cx[SIZE];
    __shared__ __align__(16) float sh_cy[SIZE];
    __shared__ __align__(16) float sh_cn[SIZE];
    __shared__ float2         sh_q[SIZE];
    __shared__ float          sh_m[SIZE];
    __shared__ unsigned short sh_idx[SIZE];
    __shared__ float          sh_red[NWARP * 3];
    __shared__ float          sh_B;
    __shared__ int            sh_last;

    // dir 0: directed(points1=pred, points2=tgt) -> queries = tgt, candidates = pred
    // dir 1: directed(points1=tgt, points2=pred) -> queries = pred, candidates = tgt
    const float* qsrc = (dir == 0) ? tgt  : pred;
    const float* csrc = (dir == 0) ? pred : tgt;
    const float* q0 = qsrc + (size_t)n * (2 * W_IN);
    const float* c0 = csrc + (size_t)n * (2 * W_IN);
    const float* v0 = vis  + (size_t)n * W_IN;

    const float delta = 127.0f / 1023.0f;

    // ---- Query + mask interpolation (all 1024; identical in all 4 splits so B
    //      is computed bit-identically task-wide). Track max |q|^2 for B. ----
    float maxSq = 0.0f;
    for (int e = tid; e < SIZE; e += NTHREADS) {
        float pos = (float)e * delta;
        int i0 = (int)pos;
        if (i0 > W_IN - 1) i0 = W_IN - 1;
        int i1 = i0 + 1; if (i1 > W_IN - 1) i1 = W_IN - 1;
        float w  = pos - (float)i0;
        float w0 = 1.0f - w;
        float qx = q0[i0]        * w0 + q0[i1]        * w;
        float qy = q0[W_IN + i0] * w0 + q0[W_IN + i1] * w;
        float mv = v0[i0]        * w0 + v0[i1]        * w;
        if (mv < 0.5f) mv = 0.0f;
        sh_q[e] = make_float2(qx, qy);
        sh_m[e] = mv;
        float sq = fmaf(qx, qx, qy * qy);
        maxSq = fmaxf(maxSq, sq);
    }
    // ---- Candidate slice interpolation (one element per thread) ----
    {
        int e = split * SLICE + tid;
        float pos = (float)e * delta;
        int i0 = (int)pos;
        if (i0 > W_IN - 1) i0 = W_IN - 1;
        int i1 = i0 + 1; if (i1 > W_IN - 1) i1 = W_IN - 1;
        float w  = pos - (float)i0;
        float w0 = 1.0f - w;
        float cx = c0[i0]        * w0 + c0[i1]        * w;
        float cy = c0[W_IN + i0] * w0 + c0[W_IN + i1] * w;
        sh_cx[tid] = cx;
        sh_cy[tid] = cy;
        sh_cn[tid] = fmaf(cx, cx, cy * cy);   // raw Cj; +B below
    }
    // CTA max-reduce for the shift constant B (identical across splits)
#pragma unroll
    for (int off = 16; off > 0; off >>= 1)
        maxSq = fmaxf(maxSq, __shfl_xor_sync(0xFFFFFFFFu, maxSq, off));
    if ((tid & 31) == 0) sh_red[tid >> 5] = maxSq;
    __syncthreads();
    if (tid == 0) {
        float m = sh_red[0];
#pragma unroll
        for (int w = 1; w < NWARP; w++) m = fmaxf(m, sh_red[w]);
        sh_B = m + 1.0f;
    }
    __syncthreads();
    const float B = sh_B;
    // Shift cn and publish this slice to global for the combiner.
    {
        float cnB = sh_cn[tid] + B;
        sh_cn[tid] = cnB;
        int jg = split * SLICE + tid;
        float* base = g_cand + (size_t)task * (3 * SIZE);
        base[jg]            = sh_cx[tid];
        base[SIZE + jg]     = sh_cy[tid];
        base[2 * SIZE + jg] = cnB;
    }
    __syncthreads();

    const ulonglong2* cx4 = (const ulonglong2*)sh_cx;   // 64 quads of the slice
    const ulonglong2* cy4 = (const ulonglong2*)sh_cy;
    const ulonglong2* cn4 = (const ulonglong2*)sh_cn;

    // ---- This thread's 4 scalar queries, duplicated-packed operands ----
    u64      m2qx2[QPT], m2qy2[QPT];
    float    mn0[QPT], mn1[QPT], mn2[QPT], mn3[QPT];   // 4 chains for ILP
    unsigned key[QPT];                  // (trunc(prefix-min) | GLOBAL group id)
    const float FMAXF = __uint_as_float(0x7F7FFFFFu);
#pragma unroll
    for (int q = 0; q < QPT; q++) {
        float2 v = sh_q[tid + q * NTHREADS];
        m2qx2[q] = pk2(-2.0f * v.x, -2.0f * v.x);
        m2qy2[q] = pk2(-2.0f * v.y, -2.0f * v.y);
        mn0[q] = FMAXF; mn1[q] = FMAXF; mn2[q] = FMAXF; mn3[q] = FMAXF;
        key[q] = 0xFFFFFFFFu;
    }

    // ---- Pass 1: scan this slice. d'' = (B + Cj) - 2qx*cx - 2qy*cy >= 1. ----
    // Group key = trunc(prefix-min) | global group id. Cross-split IMNMX later
    // picks the smallest (trunc, gid) => globally earliest group achieving the
    // global trunc-min — identical first-occurrence semantics to the unsplit
    // kernel (trunc monotone: trunc(prefix-min) = prefix-min of trunc'd d).
#pragma unroll 1
    for (int g = 0; g < NGRP_L; g++) {
        const int u0 = g * GRPQ;
#pragma unroll
        for (int t = 0; t < GRPQ; t++) {
            ulonglong2 cx2 = cx4[u0 + t];
            ulonglong2 cy2 = cy4[u0 + t];
            ulonglong2 cn2 = cn4[u0 + t];
#pragma unroll
            for (int q = 0; q < QPT; q++) {
                u64 d01 = fma2(cx2.x, m2qx2[q], fma2(cy2.x, m2qy2[q], cn2.x));
                u64 d23 = fma2(cx2.y, m2qx2[q], fma2(cy2.y, m2qy2[q], cn2.y));
                unsigned a, b, c, d; unpk2(d01, a, b); unpk2(d23, c, d);
                mn0[q] = fminf(mn0[q], __uint_as_float(a));
                mn1[q] = fminf(mn1[q], __uint_as_float(b));
                mn2[q] = fminf(mn2[q], __uint_as_float(c));
                mn3[q] = fminf(mn3[q], __uint_as_float(d));
            }
        }
        const unsigned gu = (unsigned)(split * NGRP_L + g);   // GLOBAL group id
#pragma unroll
        for (int q = 0; q < QPT; q++) {
            float m = fminf(fminf(mn0[q], mn1[q]), fminf(mn2[q], mn3[q]));
            key[q] = min(key[q], (__float_as_uint(m) & 0xFFFFFC00u) | gu);
        }
    }

    // ---- Publish keys; last split CTA of the task combines ----
    {
        unsigned* kbase = g_key + ((size_t)(task * NSPLIT + split)) * SIZE;
#pragma unroll
        for (int q = 0; q < QPT; q++)
            kbase[tid + q * NTHREADS] = key[q];
    }
    __threadfence();                     // release keys + cand slice
    __syncthreads();
    if (tid == 0) {
        unsigned t = atomicAdd(&g_tdone[task], 1u);
        sh_last = (t == NSPLIT - 1) ? 1 : 0;
    }
    __syncthreads();
    if (!sh_last) return;

    // ================= Combiner (one CTA per task) =================
    __threadfence();                     // acquire all splits' writes
    if (tid == 0) g_tdone[task] = 0;     // reset for next (graph) call

    // Reload FULL candidate set into smem
    {
        const float* base = g_cand + (size_t)task * (3 * SIZE);
        for (int e = tid; e < SIZE; e += NTHREADS) {
            sh_cx[e] = base[e];
            sh_cy[e] = base[SIZE + e];
            sh_cn[e] = base[2 * SIZE + e];
        }
    }
    __syncthreads();

    // Fold 4 split keys per query; rescan winning 16-candidate group (scalar,
    // identical rounding); exact-recompute min distance at selected index.
    const unsigned* kb = g_key + (size_t)task * NSPLIT * SIZE;
    float sum_mse = 0.0f;
#pragma unroll
    for (int q = 0; q < QPT; q++) {
        const int i = tid + q * NTHREADS;
        unsigned k0 = kb[i], k1 = kb[SIZE + i], k2 = kb[2 * SIZE + i], k3 = kb[3 * SIZE + i];
        unsigned kk = min(min(k0, k1), min(k2, k3));
        const int g = (int)(kk & 1023u);
        float2 qv = sh_q[i];
        float m2qx = -2.0f * qv.x;       // identical value to pass-1 operand
        float m2qy = -2.0f * qv.y;
        unsigned best = 0xFFFFFFFFu;
        const int j0 = g * GRP;
#pragma unroll
        for (int t = 0; t < GRP; t++) {
            int j = j0 + t;
            float d = fmaf(sh_cx[j], m2qx, fmaf(sh_cy[j], m2qy, sh_cn[j]));
            unsigned k = (__float_as_uint(d) & 0xFFFFFC00u) | (unsigned)j;
            best = min(best, k);
        }
        unsigned jsel = best & 1023u;
        sh_idx[i] = (unsigned short)jsel;
        float dx = qv.x - sh_cx[jsel];
        float dy = qv.y - sh_cy[jsel];
        sum_mse += fmaf(dx, dx, dy * dy) * sh_m[i];
    }
    __syncthreads();

    // ---- Index-order penalty + (dir 0) direct error (full query range) ----
    float sum_ord = 0.0f;
    float sum_dir = 0.0f;
#pragma unroll
    for (int q = 0; q < QPT; q++) {
        int i = tid + q * NTHREADS;
        if (i < SIZE - 1) {
            int   diff = (int)sh_idx[i + 1] - (int)sh_idx[i];
            float nd   = (float)(-diff);
            nd = nd > 0.0f ? nd : 0.0f;             // relu
            sum_ord += nd * nd * sh_m[i];
        }
        if (dir == 0) {
            float2 qv = sh_q[i];
            float dx = qv.x - sh_cx[i];
            float dy = qv.y - sh_cy[i];
            sum_dir += fmaf(dx, dx, dy * dy) * sh_m[i];
        }
    }

    // ---- CTA reduction (deterministic) ----
#pragma unroll
    for (int off = 16; off > 0; off >>= 1) {
        sum_mse += __shfl_down_sync(0xFFFFFFFFu, sum_mse, off);
        sum_ord += __shfl_down_sync(0xFFFFFFFFu, sum_ord, off);
        sum_dir += __shfl_down_sync(0xFFFFFFFFu, sum_dir, off);
    }
    const int warp = tid >> 5, lane = tid & 31;
    if (lane == 0) {
        sh_red[warp * 3 + 0] = sum_mse;
        sh_red[warp * 3 + 1] = sum_ord;
        sh_red[warp * 3 + 2] = sum_dir;
    }
    __syncthreads();
    if (tid == 0) {
        float a = 0.f, b = 0.f, c = 0.f;
#pragma unroll
        for (int w = 0; w < NWARP; w++) {
            a += sh_red[w * 3 + 0];
            b += sh_red[w * 3 + 1];
            c += sh_red[w * 3 + 2];
        }
        g_part[task] = make_float4(a, b, c, 0.0f);
        __threadfence();
        unsigned ticket = atomicAdd(&g_done, 1u);
        sh_last = (ticket == (gridDim.x >> 2) - 1) ? 1 : 0;
    }
    __syncthreads();

    // ---- Last combiner: global reduce + final formula + counter reset ----
    if (sh_last) {
        __threadfence();                 // acquire all task partials
        const int ntasks = gridDim.x >> 2;
        float a = 0.f, b = 0.f, c = 0.f;
        for (int i = tid; i < ntasks; i += NTHREADS) {
            float4 p = g_part[i];
            a += p.x; b += p.y; c += p.z;
        }
        // reuse freed candidate arrays as reduction scratch
        sh_cx[tid] = a; sh_cy[tid] = b; sh_cn[tid] = c;
        __syncthreads();
        for (int off = NTHREADS / 2; off > 0; off >>= 1) {
            if (tid < off) {
                sh_cx[tid] += sh_cx[tid + off];
                sh_cy[tid] += sh_cy[tid + off];
                sh_cn[tid] += sh_cn[tid + off];
            }
            __syncthreads();
        }
        if (tid == 0) {
            float denom_pts = (float)N * (float)SIZE;
            float matched = sh_cx[0] / (2.0f * denom_pts)
                          + POINT_ORDER_WEIGHT * sh_cy[0] /
                            (2.0f * (float)N * (float)(SIZE - 1));
            float direct  = sh_cn[0] / denom_pts;
            out[0] = fminf(matched, direct);
            g_done = 0;                  // reset for next (graph) call
        }
    }
}

extern "C" void kernel_launch(void* const* d_in, const int* in_sizes, int n_in,
                              void* d_out, int out_size)
{
    const float* tgt  = (const float*)d_in[0];
    const float* pred = (const float*)d_in[1];
    const float* vis  = (const float*)d_in[2];
    float* out = (float*)d_out;

    const int N = in_sizes[2] / W_IN;          // 128
    const int nblocks = 2 * N * NSPLIT;        // 1024 CTAs: (n, dir) x 4 slices

    chamfer_split_kernel<<<nblocks, NTHREADS>>>(tgt, pred, vis, out, N);
}

// round 17
// speedup vs baseline: 4.3487x; 4.3487x over previous
#include <cuda_runtime.h>

// Problem constants (shapes fixed by the benchmark instance)
#define W_IN      128
#define UP_FACTOR 8
#define SIZE      (W_IN * UP_FACTOR)   // 1024 interpolated points
#define NTHREADS  256                  // 8 warps/CTA, 2 CTAs/SM
#define NWARP     (NTHREADS / 32)
#define QPT       (SIZE / NTHREADS)    // max queries per thread
#define GRPQ      4                    // quads per group (16 candidates)
#define GRP       16                   // candidates per group
#define NGRP      (SIZE / GRP)         // 64 groups
#define POINT_ORDER_WEIGHT 0.1f

typedef unsigned long long u64;

// ---- Blackwell packed f32x2 helpers (sm_103a) ----
__device__ __forceinline__ u64 pk2(float lo, float hi) {
    u64 r; asm("mov.b64 %0, {%1, %2};" : "=l"(r) : "f"(lo), "f"(hi)); return r;
}
__device__ __forceinline__ u64 fma2(u64 a, u64 b, u64 c) {
    u64 r; asm("fma.rn.f32x2 %0, %1, %2, %3;" : "=l"(r) : "l"(a), "l"(b), "l"(c)); return r;
}
__device__ __forceinline__ void unpk2(u64 v, unsigned &lo, unsigned &hi) {
    asm("mov.b64 {%0, %1}, %2;" : "=r"(lo), "=r"(hi) : "l"(v));
}

// Deterministic per-CTA partials: x = sum(min_dist*m), y = sum(order_pen*m),
// z = sum(direct_err*m) [dir==0 CTAs only]
__device__ float4   g_part[1024];
__device__ unsigned g_done;            // zero-init; reset by last CTA each call

// ---- Templated scan over NQ active queries per thread (unchanged R13 math) ----
// d'' = (B + Cj) - 2qx*cx - 2qy*cy >= 1. Group key = trunc(prefix-min)|group_id.
// trunc monotone => trunc(prefix-min) = prefix-min of trunc'd d, so the key
// IMNMX picks the first group achieving the global trunc-min — the one holding
// the first global trunc-argmin. Scalar rescan (identical rounding) recovers
// the exact index; exact distance recomputed at that index.
template<int NQ>
__device__ __forceinline__ float scan_emit(
    const float* __restrict__ sh_cx, const float* __restrict__ sh_cy,
    const float* __restrict__ sh_cn, const float2* __restrict__ sh_q,
    const float* __restrict__ sh_m, unsigned short* __restrict__ sh_idx,
    const unsigned short* __restrict__ sh_act, int nact, int tid)
{
    const ulonglong2* cx4 = (const ulonglong2*)sh_cx;
    const ulonglong2* cy4 = (const ulonglong2*)sh_cy;
    const ulonglong2* cn4 = (const ulonglong2*)sh_cn;

    int  iq[NQ];
    bool val[NQ];
#pragma unroll
    for (int q = 0; q < NQ; q++) {
        int e = tid + q * NTHREADS;
        val[q] = (e < nact);
        iq[q]  = val[q] ? (int)sh_act[e] : (int)sh_act[0];
    }

    u64      m2qx2[NQ], m2qy2[NQ];
    float    mn0[NQ], mn1[NQ], mn2[NQ], mn3[NQ];  // 4 chains for ILP
    unsigned key[NQ];
    const float FMAXF = __uint_as_float(0x7F7FFFFFu);
#pragma unroll
    for (int q = 0; q < NQ; q++) {
        float2 v = sh_q[iq[q]];
        m2qx2[q] = pk2(-2.0f * v.x, -2.0f * v.x);
        m2qy2[q] = pk2(-2.0f * v.y, -2.0f * v.y);
        mn0[q] = FMAXF; mn1[q] = FMAXF; mn2[q] = FMAXF; mn3[q] = FMAXF;
        key[q] = 0xFFFFFFFFu;
    }

#pragma unroll 1
    for (int g = 0; g < NGRP; g++) {
        const int u0 = g * GRPQ;
#pragma unroll
        for (int t = 0; t < GRPQ; t++) {
            ulonglong2 cx2 = cx4[u0 + t];
            ulonglong2 cy2 = cy4[u0 + t];
            ulonglong2 cn2 = cn4[u0 + t];
#pragma unroll
            for (int q = 0; q < NQ; q++) {
                u64 d01 = fma2(cx2.x, m2qx2[q], fma2(cy2.x, m2qy2[q], cn2.x));
                u64 d23 = fma2(cx2.y, m2qx2[q], fma2(cy2.y, m2qy2[q], cn2.y));
                unsigned a, b, c, d; unpk2(d01, a, b); unpk2(d23, c, d);
                mn0[q] = fminf(mn0[q], __uint_as_float(a));
                mn1[q] = fminf(mn1[q], __uint_as_float(b));
                mn2[q] = fminf(mn2[q], __uint_as_float(c));
                mn3[q] = fminf(mn3[q], __uint_as_float(d));
            }
        }
        const unsigned gu = (unsigned)g;
#pragma unroll
        for (int q = 0; q < NQ; q++) {
            float m = fminf(fminf(mn0[q], mn1[q]), fminf(mn2[q], mn3[q]));
            key[q] = min(key[q], (__float_as_uint(m) & 0xFFFFFC00u) | gu);
        }
    }

    float sum_mse = 0.0f;
#pragma unroll
    for (int q = 0; q < NQ; q++) {
        const int g = (int)(key[q] & 1023u);
        float2 qv = sh_q[iq[q]];
        float m2qx = -2.0f * qv.x;      // identical value to pass-1 operand
        float m2qy = -2.0f * qv.y;
        unsigned best = 0xFFFFFFFFu;
        const int j0 = g * GRP;
#pragma unroll
        for (int t = 0; t < GRP; t++) {
            int j = j0 + t;
            float d = fmaf(sh_cx[j], m2qx, fmaf(sh_cy[j], m2qy, sh_cn[j]));
            unsigned k = (__float_as_uint(d) & 0xFFFFFC00u) | (unsigned)j;
            best = min(best, k);
        }
        unsigned jsel = best & 1023u;
        if (val[q]) {
            sh_idx[iq[q]] = (unsigned short)jsel;
            float dx = qv.x - sh_cx[jsel];
            float dy = qv.y - sh_cy[jsel];
            sum_mse += fmaf(dx, dx, dy * dy) * sh_m[iq[q]];
        }
    }
    return sum_mse;
}

__global__ __launch_bounds__(NTHREADS, 2)
void chamfer_fused_kernel(const float* __restrict__ tgt,
                          const float* __restrict__ pred,
                          const float* __restrict__ vis,
                          float* __restrict__ out,
                          int N)
{
    const int n   = blockIdx.x >> 1;
    const int dir = blockIdx.x & 1;
    const int tid = threadIdx.x;

    __shared__ __align__(16) float sh_cx[SIZE];   // 4 KB
    __shared__ __align__(16) float sh_cy[SIZE];   // 4 KB
    __shared__ __align__(16) float sh_cn[SIZE];   // 4 KB: Cj + B
    __shared__ float2         sh_q[SIZE];         // 8 KB queries
    __shared__ float          sh_m[SIZE];         // 4 KB thresholded mask
    __shared__ unsigned short sh_idx[SIZE];       // 2 KB argmin indices
    __shared__ unsigned short sh_act[SIZE];       // 2 KB active query list
    __shared__ float          sh_red[NWARP * 3];
    __shared__ int            sh_wsum[NWARP], sh_woff[NWARP];
    __shared__ int            sh_nact;
    __shared__ float          sh_B;
    __shared__ int            sh_last;
    __shared__ float          s_f[NTHREADS * 3];

    // dir 0: directed(points1=pred, points2=tgt) -> queries = tgt, candidates = pred
    // dir 1: directed(points1=tgt, points2=pred) -> queries = pred, candidates = tgt
    const float* qsrc = (dir == 0) ? tgt  : pred;
    const float* csrc = (dir == 0) ? pred : tgt;
    const float* q0 = qsrc + (size_t)n * (2 * W_IN);
    const float* c0 = csrc + (size_t)n * (2 * W_IN);
    const float* v0 = vis  + (size_t)n * W_IN;

    const float delta = 127.0f / 1023.0f;

    // ---- Interpolation (align_corners=True linear). Track max |q|^2 for B. ----
    float maxSq = 0.0f;
    for (int e = tid; e < SIZE; e += NTHREADS) {
        float pos = (float)e * delta;
        int i0 = (int)pos;
        if (i0 > W_IN - 1) i0 = W_IN - 1;
        int i1 = i0 + 1; if (i1 > W_IN - 1) i1 = W_IN - 1;
        float w  = pos - (float)i0;
        float w0 = 1.0f - w;

        float qx = q0[i0]        * w0 + q0[i1]        * w;
        float qy = q0[W_IN + i0] * w0 + q0[W_IN + i1] * w;
        float cx = c0[i0]        * w0 + c0[i1]        * w;
        float cy = c0[W_IN + i0] * w0 + c0[W_IN + i1] * w;
        float mv = v0[i0]        * w0 + v0[i1]        * w;
        if (mv < 0.5f) mv = 0.0f;

        sh_q[e] = make_float2(qx, qy);
        sh_m[e] = mv;
        sh_idx[e] = 0;                          // dead queries read as 0 (x0 later)
        sh_cx[e] = cx;
        sh_cy[e] = cy;
        sh_cn[e] = fmaf(cx, cx, cy * cy);       // raw Cj (B added below)
        float sq = fmaf(qx, qx, qy * qy);
        maxSq = fmaxf(maxSq, sq);
    }
    // CTA max-reduce for the shift constant B
#pragma unroll
    for (int off = 16; off > 0; off >>= 1)
        maxSq = fmaxf(maxSq, __shfl_xor_sync(0xFFFFFFFFu, maxSq, off));
    if ((tid & 31) == 0) sh_red[tid >> 5] = maxSq;
    __syncthreads();
    if (tid == 0) {
        float m = sh_red[0];
#pragma unroll
        for (int w = 1; w < NWARP; w++) m = fmaxf(m, sh_red[w]);
        sh_B = m + 1.0f;
    }
    __syncthreads();
    const float B = sh_B;
    for (int e = tid; e < SIZE; e += NTHREADS)
        sh_cn[e] += B;

    // ---- Build compacted active-query list (deterministic CTA scan). ----
    // Query i is DEAD iff m[i]==0 and m[i-1]==0: then mse term is x0 and its
    // index only appears in ord terms multiplied by m[i] or m[i-1] (both 0).
    bool act[QPT];
    int  cnt = 0;
#pragma unroll
    for (int k = 0; k < QPT; k++) {
        int i = tid + k * NTHREADS;
        bool a = (sh_m[i] > 0.0f) || (i > 0 && sh_m[i - 1] > 0.0f);
        act[k] = a;
        cnt += a ? 1 : 0;
    }
    {   // exclusive scan of per-thread counts over 256 threads
        const int lane = tid & 31, warp = tid >> 5;
        int v = cnt;
#pragma unroll
        for (int o = 1; o < 32; o <<= 1) {
            int t = __shfl_up_sync(0xFFFFFFFFu, v, o);
            if (lane >= o) v += t;
        }
        if (lane == 31) sh_wsum[warp] = v;
        __syncthreads();
        if (tid == 0) {
            int s = 0;
#pragma unroll
            for (int w = 0; w < NWARP; w++) { sh_woff[w] = s; s += sh_wsum[w]; }
            sh_nact = s;
        }
        __syncthreads();
        int pos = sh_woff[warp] + (v - cnt);
#pragma unroll
        for (int k = 0; k < QPT; k++) {
            if (act[k]) sh_act[pos++] = (unsigned short)(tid + k * NTHREADS);
        }
    }
    __syncthreads();
    const int nact = sh_nact;
    const int nq   = (nact + NTHREADS - 1) / NTHREADS;   // 0..4

    // ---- Scan only active queries (NQ-templated hot loop) ----
    float sum_mse = 0.0f;
    switch (nq) {
        case 4: sum_mse = scan_emit<4>(sh_cx, sh_cy, sh_cn, sh_q, sh_m, sh_idx, sh_act, nact, tid); break;
        case 3: sum_mse = scan_emit<3>(sh_cx, sh_cy, sh_cn, sh_q, sh_m, sh_idx, sh_act, nact, tid); break;
        case 2: sum_mse = scan_emit<2>(sh_cx, sh_cy, sh_cn, sh_q, sh_m, sh_idx, sh_act, nact, tid); break;
        case 1: sum_mse = scan_emit<1>(sh_cx, sh_cy, sh_cn, sh_q, sh_m, sh_idx, sh_act, nact, tid); break;
        default: break;                                   // nact==0
    }
    __syncthreads();

    // ---- Index-order penalty + (dir 0) direct error (full range; x0 kills dead) ----
    float sum_ord = 0.0f;
    float sum_dir = 0.0f;
#pragma unroll
    for (int q = 0; q < QPT; q++) {
        int i = tid + q * NTHREADS;
        if (i < SIZE - 1) {
            int   diff = (int)sh_idx[i + 1] - (int)sh_idx[i];
            float nd   = (float)(-diff);
            nd = nd > 0.0f ? nd : 0.0f;             // relu
            sum_ord += nd * nd * sh_m[i];
        }
        if (dir == 0) {
            float2 qv = sh_q[i];
            float dx = qv.x - sh_cx[i];
            float dy = qv.y - sh_cy[i];
            sum_dir += fmaf(dx, dx, dy * dy) * sh_m[i];
        }
    }

    // ---- CTA reduction (deterministic) ----
#pragma unroll
    for (int off = 16; off > 0; off >>= 1) {
        sum_mse += __shfl_down_sync(0xFFFFFFFFu, sum_mse, off);
        sum_ord += __shfl_down_sync(0xFFFFFFFFu, sum_ord, off);
        sum_dir += __shfl_down_sync(0xFFFFFFFFu, sum_dir, off);
    }
    const int warp = tid >> 5, lane = tid & 31;
    if (lane == 0) {
        sh_red[warp * 3 + 0] = sum_mse;
        sh_red[warp * 3 + 1] = sum_ord;
        sh_red[warp * 3 + 2] = sum_dir;
    }
    __syncthreads();
    if (tid == 0) {
        float a = 0.f, b = 0.f, c = 0.f;
#pragma unroll
        for (int w = 0; w < NWARP; w++) {
            a += sh_red[w * 3 + 0];
            b += sh_red[w * 3 + 1];
            c += sh_red[w * 3 + 2];
        }
        g_part[blockIdx.x] = make_float4(a, b, c, 0.0f);
        __threadfence();
        unsigned ticket = atomicAdd(&g_done, 1u);
        sh_last = (ticket == gridDim.x - 1) ? 1 : 0;
    }
    __syncthreads();

    // ---- Last CTA: global reduce + final formula + counter reset ----
    if (sh_last) {
        __threadfence();                        // acquire all partials
        const int nblocks = gridDim.x;
        float a = 0.f, b = 0.f, c = 0.f;
        for (int i = tid; i < nblocks; i += NTHREADS) {
            float4 p = g_part[i];
            a += p.x; b += p.y; c += p.z;
        }
        s_f[tid] = a; s_f[NTHREADS + tid] = b; s_f[2 * NTHREADS + tid] = c;
        __syncthreads();
        for (int off = NTHREADS / 2; off > 0; off >>= 1) {
            if (tid < off) {
                s_f[tid]                += s_f[tid + off];
                s_f[NTHREADS + tid]     += s_f[NTHREADS + tid + off];
                s_f[2 * NTHREADS + tid] += s_f[2 * NTHREADS + tid + off];
            }
            __syncthreads();
        }
        if (tid == 0) {
            float denom_pts = (float)N * (float)SIZE;
            float matched = s_f[0] / (2.0f * denom_pts)
                          + POINT_ORDER_WEIGHT * s_f[NTHREADS] /
                            (2.0f * (float)N * (float)(SIZE - 1));
            float direct  = s_f[2 * NTHREADS] / denom_pts;
            out[0] = fminf(matched, direct);
            g_done = 0;                         // reset for next (graph) call
        }
    }
}

extern "C" void kernel_launch(void* const* d_in, const int* in_sizes, int n_in,
                              void* d_out, int out_size)
{
    const float* tgt  = (const float*)d_in[0];
    const float* pred = (const float*)d_in[1];
    const float* vis  = (const float*)d_in[2];
    float* out = (float*)d_out;

    const int N = in_sizes[2] / W_IN;     // 128
    const int nblocks = 2 * N;            // 256 CTAs: (batch, direction)

    chamfer_fused_kernel<<<nblocks, NTHREADS>>>(tgt, pred, vis, out, N);
}